// round 15
// baseline (speedup 1.0000x reference)
#include <cuda_runtime.h>
#include <cuda_bf16.h>

// Gram-Schmidt over M=4 model outputs, per (batch, channel) vector of D=1024.
// x: [4, 128, 64, 1024] fp32, out same shape.
//
// R2:  all 10 pairwise dots G_ij in ONE fused block reduction; GS coefficients
//      are scalar algebra on G (lower-triangular T, basis_i = sum_j T_ij v_j).
// R10: LDG.256/STG.256, 128 thr/CTA, grid 8192.
// R14: single-barrier reduction (every thread sums warp rows via broadcast
//      LDS.128). kernel 37.1us, DRAM 71%.
// R15: evict-first L2 policy on STORES ONLY (loads default). The output is
//      never re-read; at default policy its 134MB of dirty lines evict x
//      between graph replays. Demoting stores lets x win L2 residency ->
//      fewer DRAM read misses. (Untested cell of the policy matrix: R5 had
//      both streams demoted, R10/R14 had both normal.)

#define NTHREADS 128
#define D_DIM 1024
#define NPAIRS 8192              // B*C
#define MSTRIDE_B 33554432u      // B*C*D*4 bytes = 32 MB

struct f8 { float4 a, b; };

__device__ __forceinline__ f8 ldg256(const void* p) {
    f8 r;
    asm("ld.global.v8.b32 {%0,%1,%2,%3,%4,%5,%6,%7}, [%8];"
        : "=f"(r.a.x), "=f"(r.a.y), "=f"(r.a.z), "=f"(r.a.w),
          "=f"(r.b.x), "=f"(r.b.y), "=f"(r.b.z), "=f"(r.b.w)
        : "l"(p));
    return r;
}

// STG.256 with L2 evict-first cache-hint policy (output: zero reuse).
__device__ __forceinline__ void stg256_ef(void* p, f8 v, unsigned long long pol) {
    asm volatile("st.global.L2::cache_hint.v8.b32 [%0], {%1,%2,%3,%4,%5,%6,%7,%8}, %9;"
                 :: "l"(p),
                    "f"(v.a.x), "f"(v.a.y), "f"(v.a.z), "f"(v.a.w),
                    "f"(v.b.x), "f"(v.b.y), "f"(v.b.z), "f"(v.b.w),
                    "l"(pol)
                 : "memory");
}

__device__ __forceinline__ float dot8(f8 u, f8 v) {
    return u.a.x * v.a.x + u.a.y * v.a.y + u.a.z * v.a.z + u.a.w * v.a.w +
           u.b.x * v.b.x + u.b.y * v.b.y + u.b.z * v.b.z + u.b.w * v.b.w;
}

__device__ __forceinline__ float4 comb4(float4 v0, float s0) {
    return make_float4(s0 * v0.x, s0 * v0.y, s0 * v0.z, s0 * v0.w);
}
__device__ __forceinline__ float4 comb4(float4 v0, float s0, float4 v1, float s1) {
    return make_float4(s0 * v0.x + s1 * v1.x, s0 * v0.y + s1 * v1.y,
                       s0 * v0.z + s1 * v1.z, s0 * v0.w + s1 * v1.w);
}
__device__ __forceinline__ float4 comb4(float4 v0, float s0, float4 v1, float s1,
                                        float4 v2, float s2) {
    return make_float4(s0 * v0.x + s1 * v1.x + s2 * v2.x,
                       s0 * v0.y + s1 * v1.y + s2 * v2.y,
                       s0 * v0.z + s1 * v1.z + s2 * v2.z,
                       s0 * v0.w + s1 * v1.w + s2 * v2.w);
}
__device__ __forceinline__ float4 comb4(float4 v0, float s0, float4 v1, float s1,
                                        float4 v2, float s2, float4 v3, float s3) {
    return make_float4(s0 * v0.x + s1 * v1.x + s2 * v2.x + s3 * v3.x,
                       s0 * v0.y + s1 * v1.y + s2 * v2.y + s3 * v3.y,
                       s0 * v0.z + s1 * v1.z + s2 * v2.z + s3 * v3.z,
                       s0 * v0.w + s1 * v1.w + s2 * v2.w + s3 * v3.w);
}

__global__ __launch_bounds__(NTHREADS, 8)
void gram_schmidt_kernel(const float* __restrict__ x, float* __restrict__ out) {
    const int tid  = threadIdx.x;
    const int lane = tid & 31;
    const int warp = tid >> 5;          // 0..3

    // per-warp partials, 12-float rows (48B): [p0..p9, pad, pad]
    __shared__ __align__(16) float red[4][12];

    // Evict-first policy for the output stream.
    unsigned long long pol;
    asm("createpolicy.fractional.L2::evict_first.b64 %0, 1.0;" : "=l"(pol));

    // byte offset: bc*4096 + tid*32, 32B-aligned, fits unsigned (max < 2^28).
    const unsigned base = blockIdx.x * (D_DIM * 4u) + (unsigned)tid * 32u;
    const char* xb = (const char*)x;
    char* ob = (char*)out;

    // 4 x LDG.256 (default policy): 1KB contiguous per warp per instruction.
    f8 v0 = ldg256(xb + base);
    f8 v1 = ldg256(xb + base + MSTRIDE_B);
    f8 v2 = ldg256(xb + base + 2u * MSTRIDE_B);
    f8 v3 = ldg256(xb + base + 3u * MSTRIDE_B);

    // 10 pairwise dot partials: (00)(01)(02)(03)(11)(12)(13)(22)(23)(33)
    float p[10];
    p[0] = dot8(v0, v0); p[1] = dot8(v0, v1); p[2] = dot8(v0, v2);
    p[3] = dot8(v0, v3); p[4] = dot8(v1, v1); p[5] = dot8(v1, v2);
    p[6] = dot8(v1, v3); p[7] = dot8(v2, v2); p[8] = dot8(v2, v3);
    p[9] = dot8(v3, v3);

    // Warp butterfly: 10 values packed as 5 x 64-bit shuffles per level.
#pragma unroll
    for (int lvl = 16; lvl >= 1; lvl >>= 1) {
#pragma unroll
        for (int q = 0; q < 5; q++) {
            unsigned long long u =
                ((unsigned long long)__float_as_uint(p[2 * q + 1]) << 32) |
                (unsigned long long)__float_as_uint(p[2 * q]);
            unsigned long long r = __shfl_xor_sync(0xffffffffu, u, lvl);
            p[2 * q]     += __uint_as_float((unsigned)r);
            p[2 * q + 1] += __uint_as_float((unsigned)(r >> 32));
        }
    }

    if (lane == 0) {
        float4* row = reinterpret_cast<float4*>(red[warp]);
        row[0] = make_float4(p[0], p[1], p[2], p[3]);
        row[1] = make_float4(p[4], p[5], p[6], p[7]);
        red[warp][8] = p[8];
        red[warp][9] = p[9];
    }
    __syncthreads();   // the ONLY barrier

    // Every thread sums the 4 warp rows itself (broadcast LDS.128).
    float4 ga, gb;
    float g23, g33;
    {
        const float4* r0 = reinterpret_cast<const float4*>(red[0]);
        const float4* r1 = reinterpret_cast<const float4*>(red[1]);
        const float4* r2 = reinterpret_cast<const float4*>(red[2]);
        const float4* r3 = reinterpret_cast<const float4*>(red[3]);
        float4 a0 = r0[0], a1 = r1[0], a2 = r2[0], a3 = r3[0];
        float4 b0 = r0[1], b1 = r1[1], b2 = r2[1], b3 = r3[1];
        float4 c0 = r0[2], c1 = r1[2], c2 = r2[2], c3 = r3[2];
        ga.x = a0.x + a1.x + a2.x + a3.x;
        ga.y = a0.y + a1.y + a2.y + a3.y;
        ga.z = a0.z + a1.z + a2.z + a3.z;
        ga.w = a0.w + a1.w + a2.w + a3.w;
        gb.x = b0.x + b1.x + b2.x + b3.x;
        gb.y = b0.y + b1.y + b2.y + b3.y;
        gb.z = b0.z + b1.z + b2.z + b3.z;
        gb.w = b0.w + b1.w + b2.w + b3.w;
        g23  = c0.x + c1.x + c2.x + c3.x;
        g33  = c0.y + c1.y + c2.y + c3.y;
    }
    const float g00 = ga.x, g01 = ga.y, g02 = ga.z, g03 = ga.w;
    const float g11 = gb.x, g12 = gb.y, g13 = gb.z, g22 = gb.w;

    // ---- scalar GS recurrence on the Gram matrix (replicated per thread) ----
    const float inv0 = (g00 > 0.f) ? rsqrtf(g00) : 0.f;

    const float c0 = g01 * inv0;
    const float n1 = fmaxf(g11 - c0 * c0, 0.f);
    const float inv1 = (n1 > 0.f) ? rsqrtf(n1) : 0.f;
    const float T10 = -c0 * inv0 * inv1;
    const float T11 = inv1;

    const float d0 = g02 * inv0;
    const float d1 = T10 * g02 + T11 * g12;
    const float n2 = fmaxf(g22 - d0 * d0 - d1 * d1, 0.f);
    const float inv2 = (n2 > 0.f) ? rsqrtf(n2) : 0.f;
    const float T20 = inv2 * (-d0 * inv0 - d1 * T10);
    const float T21 = inv2 * (-d1 * T11);
    const float T22 = inv2;

    const float e0 = g03 * inv0;
    const float e1 = T10 * g03 + T11 * g13;
    const float e2 = T20 * g03 + T21 * g13 + T22 * g23;
    const float n3 = fmaxf(g33 - e0 * e0 - e1 * e1 - e2 * e2, 0.f);
    const float inv3 = (n3 > 0.f) ? rsqrtf(n3) : 0.f;
    const float T30 = inv3 * (-e0 * inv0 - e1 * T10 - e2 * T20);
    const float T31 = inv3 * (-e1 * T11 - e2 * T21);
    const float T32 = inv3 * (-e2 * T22);
    const float T33 = inv3;

    // ---- outputs: basis_i = sum_j T_ij v_j (4 x STG.256, evict-first) ----
    f8 o;
    o.a = comb4(v0.a, inv0); o.b = comb4(v0.b, inv0);
    stg256_ef(ob + base, o, pol);

    o.a = comb4(v0.a, T10, v1.a, T11); o.b = comb4(v0.b, T10, v1.b, T11);
    stg256_ef(ob + base + MSTRIDE_B, o, pol);

    o.a = comb4(v0.a, T20, v1.a, T21, v2.a, T22);
    o.b = comb4(v0.b, T20, v1.b, T21, v2.b, T22);
    stg256_ef(ob + base + 2u * MSTRIDE_B, o, pol);

    o.a = comb4(v0.a, T30, v1.a, T31, v2.a, T32, v3.a, T33);
    o.b = comb4(v0.b, T30, v1.b, T31, v2.b, T32, v3.b, T33);
    stg256_ef(ob + base + 3u * MSTRIDE_B, o, pol);
}

extern "C" void kernel_launch(void* const* d_in, const int* in_sizes, int n_in,
                              void* d_out, int out_size) {
    const float* x = (const float*)d_in[0];
    float* out = (float*)d_out;
    gram_schmidt_kernel<<<NPAIRS, NTHREADS>>>(x, out);
}

// round 17
// speedup vs baseline: 1.0007x; 1.0007x over previous
#include <cuda_runtime.h>
#include <cuda_bf16.h>

// Gram-Schmidt over M=4 model outputs, per (batch, channel) vector of D=1024.
// x: [4, 128, 64, 1024] fp32, out same shape.
//
// FINAL FORM (= R14, the measured optimum):
// R2:  all 10 pairwise dots G_ij in ONE fused block reduction; GS coefficients
//      are scalar algebra on G (lower-triangular T, basis_i = sum_j T_ij v_j).
// R10: LDG.256/STG.256, 128 thr/CTA, grid 8192 (widest memory ops).
// R14: single-barrier reduction: warp butterfly -> lane0 STS -> ONE bar ->
//      every thread sums the 4 warp rows via broadcast LDS.128.
// Closed lines (all measured): occupancy flat 46-68%; all 4 L2-policy combos
//      <= default/default; every intra-CTA pipeline (reg/cp.async) regressed;
//      redux.f32 not on sm_100. Kernel is DRAM-bound on actual traffic
//      (~215MB @ 5.8TB/s = 37.1us; ~71% of spec = mixed R/W ceiling).

#define NTHREADS 128
#define D_DIM 1024
#define NPAIRS 8192              // B*C
#define MSTRIDE_B 33554432u      // B*C*D*4 bytes = 32 MB

struct f8 { float4 a, b; };

__device__ __forceinline__ f8 ldg256(const void* p) {
    f8 r;
    asm("ld.global.v8.b32 {%0,%1,%2,%3,%4,%5,%6,%7}, [%8];"
        : "=f"(r.a.x), "=f"(r.a.y), "=f"(r.a.z), "=f"(r.a.w),
          "=f"(r.b.x), "=f"(r.b.y), "=f"(r.b.z), "=f"(r.b.w)
        : "l"(p));
    return r;
}

__device__ __forceinline__ void stg256(void* p, f8 v) {
    asm volatile("st.global.v8.b32 [%0], {%1,%2,%3,%4,%5,%6,%7,%8};"
                 :: "l"(p),
                    "f"(v.a.x), "f"(v.a.y), "f"(v.a.z), "f"(v.a.w),
                    "f"(v.b.x), "f"(v.b.y), "f"(v.b.z), "f"(v.b.w)
                 : "memory");
}

__device__ __forceinline__ float dot8(f8 u, f8 v) {
    return u.a.x * v.a.x + u.a.y * v.a.y + u.a.z * v.a.z + u.a.w * v.a.w +
           u.b.x * v.b.x + u.b.y * v.b.y + u.b.z * v.b.z + u.b.w * v.b.w;
}

__device__ __forceinline__ float4 comb4(float4 v0, float s0) {
    return make_float4(s0 * v0.x, s0 * v0.y, s0 * v0.z, s0 * v0.w);
}
__device__ __forceinline__ float4 comb4(float4 v0, float s0, float4 v1, float s1) {
    return make_float4(s0 * v0.x + s1 * v1.x, s0 * v0.y + s1 * v1.y,
                       s0 * v0.z + s1 * v1.z, s0 * v0.w + s1 * v1.w);
}
__device__ __forceinline__ float4 comb4(float4 v0, float s0, float4 v1, float s1,
                                        float4 v2, float s2) {
    return make_float4(s0 * v0.x + s1 * v1.x + s2 * v2.x,
                       s0 * v0.y + s1 * v1.y + s2 * v2.y,
                       s0 * v0.z + s1 * v1.z + s2 * v2.z,
                       s0 * v0.w + s1 * v1.w + s2 * v2.w);
}
__device__ __forceinline__ float4 comb4(float4 v0, float s0, float4 v1, float s1,
                                        float4 v2, float s2, float4 v3, float s3) {
    return make_float4(s0 * v0.x + s1 * v1.x + s2 * v2.x + s3 * v3.x,
                       s0 * v0.y + s1 * v1.y + s2 * v2.y + s3 * v3.y,
                       s0 * v0.z + s1 * v1.z + s2 * v2.z + s3 * v3.z,
                       s0 * v0.w + s1 * v1.w + s2 * v2.w + s3 * v3.w);
}

__global__ __launch_bounds__(NTHREADS, 8)
void gram_schmidt_kernel(const float* __restrict__ x, float* __restrict__ out) {
    const int tid  = threadIdx.x;
    const int lane = tid & 31;
    const int warp = tid >> 5;          // 0..3

    // per-warp partials, 12-float rows (48B): [p0..p9, pad, pad]
    __shared__ __align__(16) float red[4][12];

    // byte offset: bc*4096 + tid*32, 32B-aligned, fits unsigned (max < 2^28).
    const unsigned base = blockIdx.x * (D_DIM * 4u) + (unsigned)tid * 32u;
    const char* xb = (const char*)x;
    char* ob = (char*)out;

    // 4 x LDG.256: 1KB contiguous per warp per instruction.
    f8 v0 = ldg256(xb + base);
    f8 v1 = ldg256(xb + base + MSTRIDE_B);
    f8 v2 = ldg256(xb + base + 2u * MSTRIDE_B);
    f8 v3 = ldg256(xb + base + 3u * MSTRIDE_B);

    // 10 pairwise dot partials: (00)(01)(02)(03)(11)(12)(13)(22)(23)(33)
    float p[10];
    p[0] = dot8(v0, v0); p[1] = dot8(v0, v1); p[2] = dot8(v0, v2);
    p[3] = dot8(v0, v3); p[4] = dot8(v1, v1); p[5] = dot8(v1, v2);
    p[6] = dot8(v1, v3); p[7] = dot8(v2, v2); p[8] = dot8(v2, v3);
    p[9] = dot8(v3, v3);

    // Warp butterfly: 10 values packed as 5 x 64-bit shuffles per level.
#pragma unroll
    for (int lvl = 16; lvl >= 1; lvl >>= 1) {
#pragma unroll
        for (int q = 0; q < 5; q++) {
            unsigned long long u =
                ((unsigned long long)__float_as_uint(p[2 * q + 1]) << 32) |
                (unsigned long long)__float_as_uint(p[2 * q]);
            unsigned long long r = __shfl_xor_sync(0xffffffffu, u, lvl);
            p[2 * q]     += __uint_as_float((unsigned)r);
            p[2 * q + 1] += __uint_as_float((unsigned)(r >> 32));
        }
    }

    if (lane == 0) {
        float4* row = reinterpret_cast<float4*>(red[warp]);
        row[0] = make_float4(p[0], p[1], p[2], p[3]);
        row[1] = make_float4(p[4], p[5], p[6], p[7]);
        red[warp][8] = p[8];
        red[warp][9] = p[9];
    }
    __syncthreads();   // the ONLY barrier

    // Every thread sums the 4 warp rows itself (broadcast LDS.128: same
    // address across the warp -> single wavefront each, conflict-free).
    float4 ga, gb;
    float g23, g33;
    {
        const float4* r0 = reinterpret_cast<const float4*>(red[0]);
        const float4* r1 = reinterpret_cast<const float4*>(red[1]);
        const float4* r2 = reinterpret_cast<const float4*>(red[2]);
        const float4* r3 = reinterpret_cast<const float4*>(red[3]);
        float4 a0 = r0[0], a1 = r1[0], a2 = r2[0], a3 = r3[0];
        float4 b0 = r0[1], b1 = r1[1], b2 = r2[1], b3 = r3[1];
        float4 c0 = r0[2], c1 = r1[2], c2 = r2[2], c3 = r3[2];
        ga.x = a0.x + a1.x + a2.x + a3.x;
        ga.y = a0.y + a1.y + a2.y + a3.y;
        ga.z = a0.z + a1.z + a2.z + a3.z;
        ga.w = a0.w + a1.w + a2.w + a3.w;
        gb.x = b0.x + b1.x + b2.x + b3.x;
        gb.y = b0.y + b1.y + b2.y + b3.y;
        gb.z = b0.z + b1.z + b2.z + b3.z;
        gb.w = b0.w + b1.w + b2.w + b3.w;
        g23  = c0.x + c1.x + c2.x + c3.x;
        g33  = c0.y + c1.y + c2.y + c3.y;
    }
    const float g00 = ga.x, g01 = ga.y, g02 = ga.z, g03 = ga.w;
    const float g11 = gb.x, g12 = gb.y, g13 = gb.z, g22 = gb.w;

    // ---- scalar GS recurrence on the Gram matrix (replicated per thread) ----
    const float inv0 = (g00 > 0.f) ? rsqrtf(g00) : 0.f;

    const float c0 = g01 * inv0;
    const float n1 = fmaxf(g11 - c0 * c0, 0.f);
    const float inv1 = (n1 > 0.f) ? rsqrtf(n1) : 0.f;
    const float T10 = -c0 * inv0 * inv1;
    const float T11 = inv1;

    const float d0 = g02 * inv0;
    const float d1 = T10 * g02 + T11 * g12;
    const float n2 = fmaxf(g22 - d0 * d0 - d1 * d1, 0.f);
    const float inv2 = (n2 > 0.f) ? rsqrtf(n2) : 0.f;
    const float T20 = inv2 * (-d0 * inv0 - d1 * T10);
    const float T21 = inv2 * (-d1 * T11);
    const float T22 = inv2;

    const float e0 = g03 * inv0;
    const float e1 = T10 * g03 + T11 * g13;
    const float e2 = T20 * g03 + T21 * g13 + T22 * g23;
    const float n3 = fmaxf(g33 - e0 * e0 - e1 * e1 - e2 * e2, 0.f);
    const float inv3 = (n3 > 0.f) ? rsqrtf(n3) : 0.f;
    const float T30 = inv3 * (-e0 * inv0 - e1 * T10 - e2 * T20);
    const float T31 = inv3 * (-e1 * T11 - e2 * T21);
    const float T32 = inv3 * (-e2 * T22);
    const float T33 = inv3;

    // ---- outputs: basis_i = sum_j T_ij v_j (4 x STG.256) ----
    f8 o;
    o.a = comb4(v0.a, inv0); o.b = comb4(v0.b, inv0);
    stg256(ob + base, o);

    o.a = comb4(v0.a, T10, v1.a, T11); o.b = comb4(v0.b, T10, v1.b, T11);
    stg256(ob + base + MSTRIDE_B, o);

    o.a = comb4(v0.a, T20, v1.a, T21, v2.a, T22);
    o.b = comb4(v0.b, T20, v1.b, T21, v2.b, T22);
    stg256(ob + base + 2u * MSTRIDE_B, o);

    o.a = comb4(v0.a, T30, v1.a, T31, v2.a, T32, v3.a, T33);
    o.b = comb4(v0.b, T30, v1.b, T31, v2.b, T32, v3.b, T33);
    stg256(ob + base + 3u * MSTRIDE_B, o);
}

extern "C" void kernel_launch(void* const* d_in, const int* in_sizes, int n_in,
                              void* d_out, int out_size) {
    const float* x = (const float*)d_in[0];
    float* out = (float*)d_out;
    gram_schmidt_kernel<<<NPAIRS, NTHREADS>>>(x, out);
}